// round 2
// baseline (speedup 1.0000x reference)
#include <cuda_runtime.h>
#include <float.h>

#define N_VEC   32768
#define DIM     256
#define KCODES  1024
#define M_BLK   64
#define KT      256
#define DC      32
#define THREADS 256

// -------- device scratch (static globals: no allocation allowed) ----------
__device__ float  g_xT[DIM * N_VEC];      // x transposed  [D][N]  (32 MB)
__device__ float  g_eT[KCODES * DIM];     // E transposed  [K][D]  (1 MB)
__device__ float  g_enorm2[KCODES];       // fp32(exact ||e_k||^2)
__device__ double g_loss;                 // loss accumulator

// -------- transpose x [N][D] -> xT [D][N] ---------------------------------
__global__ void transpose_x_kernel(const float* __restrict__ x) {
    __shared__ float tile[32][33];
    int n0 = blockIdx.x * 32;
    int d0 = blockIdx.y * 32;
    int tx = threadIdx.x, ty = threadIdx.y;
#pragma unroll
    for (int i = ty; i < 32; i += 8)
        tile[i][tx] = x[(size_t)(n0 + i) * DIM + d0 + tx];
    __syncthreads();
#pragma unroll
    for (int j = ty; j < 32; j += 8)
        g_xT[(size_t)(d0 + j) * N_VEC + n0 + tx] = tile[tx][j];
}

// -------- transpose E [D][K] -> eT [K][D] ----------------------------------
__global__ void transpose_e_kernel(const float* __restrict__ e) {
    __shared__ float tile[32][33];
    int k0 = blockIdx.x * 32;
    int d0 = blockIdx.y * 32;
    int tx = threadIdx.x, ty = threadIdx.y;
#pragma unroll
    for (int i = ty; i < 32; i += 8)
        tile[i][tx] = e[(size_t)(d0 + i) * KCODES + k0 + tx];
    __syncthreads();
#pragma unroll
    for (int j = ty; j < 32; j += 8)
        g_eT[(size_t)(k0 + j) * DIM + d0 + tx] = tile[tx][j];
}

// -------- ||e_k||^2 (double -> correctly rounded fp32); zero loss ----------
__global__ void enorm_kernel() {
    int k    = blockIdx.x * 8 + (threadIdx.x >> 5);
    int lane = threadIdx.x & 31;
    const float* row = g_eT + (size_t)k * DIM;
    double s = 0.0;
#pragma unroll
    for (int j = 0; j < 8; j++) {
        double v = (double)row[lane + 32 * j];
        s += v * v;
    }
#pragma unroll
    for (int off = 16; off; off >>= 1)
        s += __shfl_xor_sync(0xffffffffu, s, off);
    if (lane == 0) g_enorm2[k] = (float)s;
    if (blockIdx.x == 0 && threadIdx.x == 0) g_loss = 0.0;
}

// lexicographic (value, index) comparison: smaller value, then smaller index
__device__ __forceinline__ bool better(float v, int k, float v2, int k2) {
    return (v < v2) || (v == v2 && k < k2);
}

// merge sorted pair (v1,k1)<=(v2,k2) with (ov1,ok1)<=(ov2,ok2) -> top2
__device__ __forceinline__ void merge_top2(float& v1, int& k1, float& v2, int& k2,
                                           float ov1, int ok1, float ov2, int ok2) {
    float m1v, m2v; int m1k, m2k;
    if (better(v1, k1, ov1, ok1)) {
        m1v = v1; m1k = k1;
        if (better(v2, k2, ov1, ok1)) { m2v = v2; m2k = k2; }
        else                          { m2v = ov1; m2k = ok1; }
    } else {
        m1v = ov1; m1k = ok1;
        if (better(ov2, ok2, v1, k1)) { m2v = ov2; m2k = ok2; }
        else                          { m2v = v1;  m2k = k1;  }
    }
    v1 = m1v; k1 = m1k; v2 = m2v; k2 = m2k;
}

// -------- main: GEMM + top2 argmin + tie recheck + gather + out + loss -----
__global__ void __launch_bounds__(THREADS, 1)
vq_main_kernel(const float* __restrict__ x,
               const float* __restrict__ emb,
               float* __restrict__ out) {
    extern __shared__ float smem[];
    float* As = smem;                               // [256][64]  (64 KB)
    float* Bs = smem + DIM * M_BLK;                 // 2 x [32][256] (64 KB)
    int* best_idx = (int*)(Bs + 2 * DC * KT);       // [64]

    int tid = threadIdx.x;
    int m0  = blockIdx.x * M_BLK;

    // Load x tile (transposed layout): As[d][m] = xT[d][m0+m]
#pragma unroll
    for (int i = tid; i < DIM * M_BLK / 4; i += THREADS) {
        int d  = i >> 4;
        int m4 = (i & 15) << 2;
        *(float4*)(As + d * M_BLK + m4) =
            *(const float4*)(g_xT + (size_t)d * N_VEC + m0 + m4);
    }
    __syncthreads();

    int ty = tid >> 5;   // 0..7 : warp, owns vectors ty*8 .. ty*8+7
    int tx = tid & 31;   // lane

    // running top-2 per owned vector (replicated across lanes after merges)
    float rv1[8], rv2[8];
    int   rk1[8], rk2[8];
#pragma unroll
    for (int i = 0; i < 8; i++) {
        rv1[i] = FLT_MAX; rv2[i] = FLT_MAX;
        rk1[i] = 0x7fffffff; rk2[i] = 0x7fffffff;
    }

    for (int kt = 0; kt < KCODES / KT; kt++) {
        int k0 = kt * KT;
        float acc[8][8];
#pragma unroll
        for (int i = 0; i < 8; i++)
#pragma unroll
            for (int j = 0; j < 8; j++) acc[i][j] = 0.f;

        // preload first D-chunk of E tile
#pragma unroll
        for (int r = 0; r < 8; r++) {
            int f4  = r * THREADS + tid;
            int dd  = f4 >> 6;
            int kk4 = (f4 & 63) << 2;
            *(float4*)(Bs + dd * KT + kk4) =
                *(const float4*)(emb + (size_t)dd * KCODES + k0 + kk4);
        }
        __syncthreads();

        for (int dc = 0; dc < DIM / DC; dc++) {
            const float* Bcur = Bs + (dc & 1) * (DC * KT);
            if (dc + 1 < DIM / DC) {
                float* Bnxt = Bs + ((dc + 1) & 1) * (DC * KT);
                int dbase = (dc + 1) * DC;
#pragma unroll
                for (int r = 0; r < 8; r++) {
                    int f4  = r * THREADS + tid;
                    int dd  = f4 >> 6;
                    int kk4 = (f4 & 63) << 2;
                    *(float4*)(Bnxt + dd * KT + kk4) =
                        *(const float4*)(emb + (size_t)(dbase + dd) * KCODES + k0 + kk4);
                }
            }
#pragma unroll 8
            for (int dd = 0; dd < DC; dd++) {
                int d = dc * DC + dd;
                float a[8], b[8];
                *(float4*)(a)     = *(const float4*)(As + d * M_BLK + ty * 8);
                *(float4*)(a + 4) = *(const float4*)(As + d * M_BLK + ty * 8 + 4);
#pragma unroll
                for (int j = 0; j < 8; j++) b[j] = Bcur[dd * KT + tx + 32 * j];
#pragma unroll
                for (int i = 0; i < 8; i++)
#pragma unroll
                    for (int j = 0; j < 8; j++)
                        acc[i][j] = fmaf(a[i], b[j], acc[i][j]);
            }
            __syncthreads();
        }

        // scores: s = ||e||^2 - 2 f.e ; per-vector top-2 with first-index ties
#pragma unroll
        for (int i = 0; i < 8; i++) {
            float tv1 = FLT_MAX, tv2 = FLT_MAX;
            int   tk1 = 0x7fffffff, tk2 = 0x7fffffff;
#pragma unroll
            for (int j = 0; j < 8; j++) {        // j ascending == k ascending
                int   k = k0 + tx + 32 * j;
                float s = fmaf(-2.f, acc[i][j], g_enorm2[k]);
                if (s < tv1)       { tv2 = tv1; tk2 = tk1; tv1 = s; tk1 = k; }
                else if (s < tv2)  { tv2 = s;   tk2 = k; }
            }
            // warp butterfly: all lanes end with the warp-wide top2
#pragma unroll
            for (int off = 16; off; off >>= 1) {
                float ov1 = __shfl_xor_sync(0xffffffffu, tv1, off);
                int   ok1 = __shfl_xor_sync(0xffffffffu, tk1, off);
                float ov2 = __shfl_xor_sync(0xffffffffu, tv2, off);
                int   ok2 = __shfl_xor_sync(0xffffffffu, tk2, off);
                merge_top2(tv1, tk1, tv2, tk2, ov1, ok1, ov2, ok2);
            }
            merge_top2(rv1[i], rk1[i], rv2[i], rk2[i], tv1, tk1, tv2, tk2);
        }
    }

    // decide winner per vector; near-ties rechecked in double with
    // reference-rounding emulation (d = rn(rn(A - 2B) + C), tie -> smaller k)
#pragma unroll 1
    for (int i = 0; i < 8; i++) {
        int widx = rk1[i];
        if (rv2[i] - rv1[i] < 3e-4f) {
            int n  = m0 + ty * 8 + i;
            int ka = min(rk1[i], rk2[i]);
            int kb = max(rk1[i], rk2[i]);
            const float* xr = x + (size_t)n * DIM;
            const float* ea = g_eT + (size_t)ka * DIM;
            const float* eb = g_eT + (size_t)kb * DIM;
            double sA = 0.0, sBa = 0.0, sBb = 0.0;
#pragma unroll
            for (int j = 0; j < 8; j++) {
                int d = tx + 32 * j;
                double xv = (double)xr[d];
                sA  += xv * xv;
                sBa += xv * (double)ea[d];
                sBb += xv * (double)eb[d];
            }
#pragma unroll
            for (int off = 16; off; off >>= 1) {
                sA  += __shfl_xor_sync(0xffffffffu, sA,  off);
                sBa += __shfl_xor_sync(0xffffffffu, sBa, off);
                sBb += __shfl_xor_sync(0xffffffffu, sBb, off);
            }
            float A32 = (float)sA;
            float Ba  = (float)sBa;
            float Bb  = (float)sBb;
            float Ca  = g_enorm2[ka];
            float Cb  = g_enorm2[kb];
            int   ab  = __float_as_int(A32);
            int votes = 0;
#pragma unroll
            for (int jj = -2; jj <= 2; jj++) {
                int w = 3 - (jj < 0 ? -jj : jj);     // weights 1,2,3,2,1 (sum 9)
                float Aj = __int_as_float(ab + jj);
                float da = __fadd_rn(__fsub_rn(Aj, __fmul_rn(2.f, Ba)), Ca);
                float db = __fadd_rn(__fsub_rn(Aj, __fmul_rn(2.f, Bb)), Cb);
                if (da <= db) votes += w;            // tie -> smaller index ka
            }
            widx = (votes >= 5) ? ka : kb;
        }
        if (tx == 0) best_idx[ty * 8 + i] = widx;
    }
    __syncthreads();

    // epilogue: gather q, write out = x + (q - x), accumulate loss
    float lsum = 0.f;
    for (int m = 0; m < M_BLK; m++) {
        int idx  = best_idx[m];
        float q  = g_eT[(size_t)idx * DIM + tid];
        float xv = x[(size_t)(m0 + m) * DIM + tid];
        float st = __fadd_rn(xv, __fsub_rn(q, xv));   // match ref rounding
        out[(size_t)(m0 + m) * DIM + tid] = st;
        float dq = __fsub_rn(q, xv);
        lsum = fmaf(dq, dq, lsum);
    }
#pragma unroll
    for (int off = 16; off; off >>= 1)
        lsum += __shfl_xor_sync(0xffffffffu, lsum, off);
    __shared__ float wsum[8];
    if ((tid & 31) == 0) wsum[tid >> 5] = lsum;
    __syncthreads();
    if (tid == 0) {
        float t = 0.f;
#pragma unroll
        for (int w = 0; w < 8; w++) t += wsum[w];
        atomicAdd(&g_loss, (double)t);
    }
}

__global__ void finalize_kernel(float* __restrict__ out, long long loss_index) {
    if (threadIdx.x == 0) {
        float m = (float)(g_loss / (double)((long long)N_VEC * DIM));
        out[loss_index] = __fadd_rn(__fmul_rn(0.25f, m), m);  // beta*c + cb
    }
}

// ---------------------------------------------------------------------------
extern "C" void kernel_launch(void* const* d_in, const int* in_sizes, int n_in,
                              void* d_out, int out_size) {
    const float* x   = (const float*)d_in[0];
    const float* emb = (const float*)d_in[1];
    float* out = (float*)d_out;

    dim3 tb(32, 8);
    transpose_x_kernel<<<dim3(N_VEC / 32, DIM / 32), tb>>>(x);
    transpose_e_kernel<<<dim3(KCODES / 32, DIM / 32), tb>>>(emb);
    enorm_kernel<<<KCODES / 8, 256>>>();

    size_t smem = (size_t)(DIM * M_BLK + 2 * DC * KT) * sizeof(float)
                + (size_t)M_BLK * sizeof(int) + 64;
    cudaFuncSetAttribute(vq_main_kernel,
                         cudaFuncAttributeMaxDynamicSharedMemorySize, (int)smem);
    vq_main_kernel<<<N_VEC / M_BLK, THREADS, smem>>>(x, emb, out);

    finalize_kernel<<<1, 32>>>(out, (long long)out_size - 1);
}